// round 4
// baseline (speedup 1.0000x reference)
#include <cuda_runtime.h>
#include <cstdint>
#include <math.h>

// Problem constants
#define B       2
#define S       2048
#define D       1024
#define HEADS   16
#define DH      64
#define INNER   1024
#define D3      3072
#define ROWS    4096
#define ATTN_SCALE 0.125f
#define LN_EPS  1e-5f

// Scratch: xn | qkv | ctx | w_qkv rounded | w_out rounded
__device__ float g_scratch[(size_t)ROWS * D + (size_t)ROWS * D3 + (size_t)ROWS * D
                           + (size_t)D * D3 + (size_t)D * D];

// ---------------------------------------------------------------------------
// Helpers
// ---------------------------------------------------------------------------
__device__ __forceinline__ uint32_t smem_u32(const void* p) {
    uint32_t a;
    asm("{ .reg .u64 t; cvta.to.shared.u64 t, %1; cvt.u32.u64 %0, t; }" : "=r"(a) : "l"(p));
    return a;
}
__device__ __forceinline__ float tf32r(float x) {
    uint32_t o;
    asm("cvt.rna.tf32.f32 %0, %1;" : "=r"(o) : "f"(x));
    return __uint_as_float(o);
}

#define CP_ASYNC16(dst, src) \
    asm volatile("cp.async.cg.shared.global [%0], [%1], 16;" :: "r"(dst), "l"(src))
#define CP_COMMIT()  asm volatile("cp.async.commit_group;" ::: "memory")
#define CP_WAIT1()   asm volatile("cp.async.wait_group 1;" ::: "memory")
#define CP_WAIT0()   asm volatile("cp.async.wait_group 0;" ::: "memory")

__device__ __forceinline__ void mma_tf32(
    float& d0, float& d1, float& d2, float& d3,
    uint32_t a0, uint32_t a1, uint32_t a2, uint32_t a3,
    uint32_t b0, uint32_t b1)
{
    asm volatile(
        "mma.sync.aligned.m16n8k8.row.col.f32.tf32.tf32.f32 "
        "{%0,%1,%2,%3}, {%4,%5,%6,%7}, {%8,%9}, {%0,%1,%2,%3};"
        : "+f"(d0), "+f"(d1), "+f"(d2), "+f"(d3)
        : "r"(a0), "r"(a1), "r"(a2), "r"(a3), "r"(b0), "r"(b1));
}

// ---------------------------------------------------------------------------
// LayerNorm (output rounded to tf32)
// ---------------------------------------------------------------------------
__global__ __launch_bounds__(256) void ln_kernel(
    const float* __restrict__ x, const float* __restrict__ gamma,
    const float* __restrict__ beta, float* __restrict__ y)
{
    const int row = blockIdx.x;
    const int t = threadIdx.x;
    const float4* xp = (const float4*)(x + (size_t)row * D);
    float4 v = xp[t];
    float s  = v.x + v.y + v.z + v.w;
    float ss = v.x * v.x + v.y * v.y + v.z * v.z + v.w * v.w;
    #pragma unroll
    for (int off = 16; off > 0; off >>= 1) {
        s  += __shfl_down_sync(0xffffffffu, s,  off);
        ss += __shfl_down_sync(0xffffffffu, ss, off);
    }
    __shared__ float sh_s[8], sh_ss[8];
    const int w = t >> 5, lane = t & 31;
    if (lane == 0) { sh_s[w] = s; sh_ss[w] = ss; }
    __syncthreads();
    __shared__ float mu_sh, rstd_sh;
    if (t == 0) {
        float S0 = 0.f, SS0 = 0.f;
        #pragma unroll
        for (int i = 0; i < 8; i++) { S0 += sh_s[i]; SS0 += sh_ss[i]; }
        const float mu  = S0 * (1.0f / D);
        const float var = SS0 * (1.0f / D) - mu * mu;
        mu_sh = mu;
        rstd_sh = rsqrtf(var + LN_EPS);
    }
    __syncthreads();
    const float mu = mu_sh, rstd = rstd_sh;
    float4 g  = ((const float4*)gamma)[t];
    float4 bb = ((const float4*)beta)[t];
    float4 o;
    o.x = tf32r((v.x - mu) * rstd * g.x + bb.x);
    o.y = tf32r((v.y - mu) * rstd * g.y + bb.y);
    o.z = tf32r((v.z - mu) * rstd * g.z + bb.z);
    o.w = tf32r((v.w - mu) * rstd * g.w + bb.w);
    ((float4*)(y + (size_t)row * D))[t] = o;
}

// ---------------------------------------------------------------------------
// Round a weight array to tf32 (rna)
// ---------------------------------------------------------------------------
__global__ __launch_bounds__(256) void round_kernel(
    const float* __restrict__ src, float* __restrict__ dst, int n4)
{
    int i = blockIdx.x * 256 + threadIdx.x;
    if (i < n4) {
        float4 v = ((const float4*)src)[i];
        v.x = tf32r(v.x); v.y = tf32r(v.y); v.z = tf32r(v.z); v.w = tf32r(v.w);
        ((float4*)dst)[i] = v;
    }
}

// ---------------------------------------------------------------------------
// TF32 mma.sync GEMM: C[M,N] = A[M,K=1024] @ W[K,N] (+bias)
// 128x128 tile, BK=32, 256 threads (8 warps, warp-tile 32x64).
// 3-stage cp.async pipeline, ONE __syncthreads per k-chunk.
// ---------------------------------------------------------------------------
#define GA_P 36
#define GB_P 136
#define GA_ST (128 * GA_P)
#define GB_ST (32 * GB_P)
#define GEMM_SMEM (3 * (GA_ST + GB_ST) * 4)   // 107520 B

__device__ __forceinline__ void gm_load(
    uint32_t aB, uint32_t bB,
    const float* __restrict__ A, const float* __restrict__ W,
    int bm, int bn, int k0, int N, int tid)
{
    #pragma unroll
    for (int j = 0; j < 4; j++) {
        const int idx = tid + j * 256;
        const int r = idx >> 3, c = idx & 7;
        CP_ASYNC16(aB + (uint32_t)(r * GA_P + c * 4) * 4u,
                   A + (size_t)(bm + r) * D + k0 + c * 4);
    }
    #pragma unroll
    for (int j = 0; j < 4; j++) {
        const int idx = tid + j * 256;
        const int r = idx >> 5, c = idx & 31;
        CP_ASYNC16(bB + (uint32_t)(r * GB_P + c * 4) * 4u,
                   W + (size_t)(k0 + r) * N + bn + c * 4);
    }
    CP_COMMIT();
}

__global__ __launch_bounds__(256, 2) void gemm_kernel(
    const float* __restrict__ A, const float* __restrict__ W,
    const float* __restrict__ bias, float* __restrict__ C,
    int N, int round_out)
{
    extern __shared__ float sm[];
    const int tid = threadIdx.x;
    const int wid = tid >> 5, lane = tid & 31;
    const int gID = lane >> 2, tg = lane & 3;
    const int bm = blockIdx.y * 128, bn = blockIdx.x * 128;
    const int wm = (wid & 3) * 32, wn = (wid >> 2) * 64;

    float* Asm[3] = { sm, sm + (GA_ST + GB_ST), sm + 2 * (GA_ST + GB_ST) };
    float* Bsm[3] = { Asm[0] + GA_ST, Asm[1] + GA_ST, Asm[2] + GA_ST };
    const uint32_t aB[3] = { smem_u32(Asm[0]), smem_u32(Asm[1]), smem_u32(Asm[2]) };
    const uint32_t bB[3] = { smem_u32(Bsm[0]), smem_u32(Bsm[1]), smem_u32(Bsm[2]) };

    float acc[2][8][4];
    #pragma unroll
    for (int im = 0; im < 2; im++)
        #pragma unroll
        for (int n = 0; n < 8; n++)
            #pragma unroll
            for (int j = 0; j < 4; j++) acc[im][n][j] = 0.f;

    // prologue: chunks 0,1 -> stages 0,1
    gm_load(aB[0], bB[0], A, W, bm, bn, 0, N, tid);
    gm_load(aB[1], bB[1], A, W, bm, bn, 32, N, tid);

    for (int i = 0; i < 32; i++) {
        const int s = i - (i / 3) * 3;   // i % 3
        if (i < 31) { CP_WAIT1(); } else { CP_WAIT0(); }
        __syncthreads();
        if (i + 2 < 32) {
            const int s2 = (i + 2) - ((i + 2) / 3) * 3;
            gm_load(aB[s2], bB[s2], A, W, bm, bn, (i + 2) * 32, N, tid);
        }

        const float* as = Asm[s];
        const float* bs = Bsm[s];
        #pragma unroll
        for (int ks = 0; ks < 4; ks++) {
            const int k = ks * 8;
            uint32_t af[2][4];
            #pragma unroll
            for (int im = 0; im < 2; im++) {
                const float* p = as + (wm + im * 16 + gID) * GA_P + k + tg;
                af[im][0] = __float_as_uint(p[0]);
                af[im][1] = __float_as_uint(p[8 * GA_P]);
                af[im][2] = __float_as_uint(p[4]);
                af[im][3] = __float_as_uint(p[8 * GA_P + 4]);
            }
            #pragma unroll
            for (int n = 0; n < 8; n++) {
                const float* p = bs + (k + tg) * GB_P + wn + n * 8 + gID;
                const uint32_t b0 = __float_as_uint(p[0]);
                const uint32_t b1 = __float_as_uint(p[4 * GB_P]);
                #pragma unroll
                for (int im = 0; im < 2; im++)
                    mma_tf32(acc[im][n][0], acc[im][n][1], acc[im][n][2], acc[im][n][3],
                             af[im][0], af[im][1], af[im][2], af[im][3], b0, b1);
            }
        }
    }

    // epilogue
    #pragma unroll
    for (int im = 0; im < 2; im++) {
        const int r0 = bm + wm + im * 16 + gID;
        #pragma unroll
        for (int n = 0; n < 8; n++) {
            const int col = bn + wn + n * 8 + 2 * tg;
            float v0 = acc[im][n][0], v1 = acc[im][n][1];
            float v2 = acc[im][n][2], v3 = acc[im][n][3];
            if (bias) {
                const float b0 = bias[col], b1 = bias[col + 1];
                v0 += b0; v1 += b1; v2 += b0; v3 += b1;
            }
            if (round_out) {
                v0 = tf32r(v0); v1 = tf32r(v1); v2 = tf32r(v2); v3 = tf32r(v3);
            }
            *(float2*)&C[(size_t)r0 * N + col]       = make_float2(v0, v1);
            *(float2*)&C[(size_t)(r0 + 8) * N + col] = make_float2(v2, v3);
        }
    }
}

// ---------------------------------------------------------------------------
// TF32 mma.sync flash attention.
// 512 threads / 16 warps, 256 queries per block (16/warp), 64-key tiles,
// 3-stage cp.async K/V pipeline, one __syncthreads per tile.
// grid (S/256, HEADS, B)
// ---------------------------------------------------------------------------
#define KP 68
#define VP 72
#define PP 68
#define K_ST (64 * KP)
#define V_ST (64 * VP)
#define KV_ST (K_ST + V_ST)
#define ATTN_SMEM ((3 * KV_ST + 256 * PP) * 4)   // 177152 B

__device__ __forceinline__ void at_load(
    uint32_t kBs, uint32_t vBs,
    const float* __restrict__ kbase, const float* __restrict__ vbase,
    int r0, int tid)
{
    #pragma unroll
    for (int j = 0; j < 2; j++) {
        const int idx = tid + j * 512;
        const int r = idx >> 4, c = (idx & 15) * 4;
        CP_ASYNC16(kBs + (uint32_t)(r * KP + c) * 4u, kbase + (size_t)(r0 + r) * D3 + c);
        CP_ASYNC16(vBs + (uint32_t)(r * VP + c) * 4u, vbase + (size_t)(r0 + r) * D3 + c);
    }
    CP_COMMIT();
}

__global__ __launch_bounds__(512, 1) void attn_kernel(
    const float* __restrict__ qkv, float* __restrict__ ctx)
{
    extern __shared__ float sm[];
    float* Ksm[3] = { sm, sm + KV_ST, sm + 2 * KV_ST };
    float* Vsm[3] = { Ksm[0] + K_ST, Ksm[1] + K_ST, Ksm[2] + K_ST };
    float* Psm = sm + 3 * KV_ST;
    const uint32_t kB[3] = { smem_u32(Ksm[0]), smem_u32(Ksm[1]), smem_u32(Ksm[2]) };
    const uint32_t vB[3] = { smem_u32(Vsm[0]), smem_u32(Vsm[1]), smem_u32(Vsm[2]) };

    const int tid = threadIdx.x;
    const int wid = tid >> 5, lane = tid & 31;
    const int gID = lane >> 2, tg = lane & 3;
    const int h = blockIdx.y, bb = blockIdx.z;
    const int qbase = blockIdx.x * 256 + wid * 16;

    const float* qp = qkv + (size_t)(bb * S + qbase) * D3 + h * DH;
    const float* kbase = qkv + (size_t)bb * S * D3 + INNER + h * DH;
    const float* vbase = kbase + INNER;

    // Q fragments in registers (x0.125 exact power of 2, stays tf32)
    uint32_t qf[8][4];
    #pragma unroll
    for (int kf = 0; kf < 8; kf++) {
        const int k = kf * 8;
        qf[kf][0] = __float_as_uint(qp[(size_t)gID * D3 + k + tg] * ATTN_SCALE);
        qf[kf][1] = __float_as_uint(qp[(size_t)(gID + 8) * D3 + k + tg] * ATTN_SCALE);
        qf[kf][2] = __float_as_uint(qp[(size_t)gID * D3 + k + tg + 4] * ATTN_SCALE);
        qf[kf][3] = __float_as_uint(qp[(size_t)(gID + 8) * D3 + k + tg + 4] * ATTN_SCALE);
    }

    float o[8][4];
    #pragma unroll
    for (int n = 0; n < 8; n++)
        #pragma unroll
        for (int j = 0; j < 4; j++) o[n][j] = 0.f;
    float m0 = -1e30f, m1 = -1e30f, l0 = 0.f, l1 = 0.f;

    // prologue: tiles 0,1 -> stages 0,1
    at_load(kB[0], vB[0], kbase, vbase, 0, tid);
    at_load(kB[1], vB[1], kbase, vbase, 64, tid);

    const int prow = wid * 16 + gID;

    for (int i = 0; i < 32; i++) {
        const int s = i - (i / 3) * 3;
        if (i < 31) { CP_WAIT1(); } else { CP_WAIT0(); }
        __syncthreads();
        if (i + 2 < 32) {
            const int s2 = (i + 2) - ((i + 2) / 3) * 3;
            at_load(kB[s2], vB[s2], kbase, vbase, (i + 2) * 64, tid);
        }

        // ---- S = Q @ K^T ----
        float sa[8][4];
        #pragma unroll
        for (int n = 0; n < 8; n++)
            #pragma unroll
            for (int j = 0; j < 4; j++) sa[n][j] = 0.f;
        const float* ks = Ksm[s];
        #pragma unroll
        for (int kf = 0; kf < 8; kf++) {
            const int k = kf * 8;
            #pragma unroll
            for (int n = 0; n < 8; n++) {
                const float* p = ks + (n * 8 + gID) * KP + k + tg;
                mma_tf32(sa[n][0], sa[n][1], sa[n][2], sa[n][3],
                         qf[kf][0], qf[kf][1], qf[kf][2], qf[kf][3],
                         __float_as_uint(p[0]), __float_as_uint(p[4]));
            }
        }

        // ---- online softmax ----
        float rmax0 = sa[0][0], rmax1 = sa[0][2];
        #pragma unroll
        for (int n = 0; n < 8; n++) {
            rmax0 = fmaxf(rmax0, fmaxf(sa[n][0], sa[n][1]));
            rmax1 = fmaxf(rmax1, fmaxf(sa[n][2], sa[n][3]));
        }
        rmax0 = fmaxf(rmax0, __shfl_xor_sync(0xffffffffu, rmax0, 1));
        rmax0 = fmaxf(rmax0, __shfl_xor_sync(0xffffffffu, rmax0, 2));
        rmax1 = fmaxf(rmax1, __shfl_xor_sync(0xffffffffu, rmax1, 1));
        rmax1 = fmaxf(rmax1, __shfl_xor_sync(0xffffffffu, rmax1, 2));
        const float nm0 = fmaxf(m0, rmax0), nm1 = fmaxf(m1, rmax1);
        const float c0 = __expf(m0 - nm0), c1 = __expf(m1 - nm1);
        m0 = nm0; m1 = nm1;
        float s0 = 0.f, s1 = 0.f;
        #pragma unroll
        for (int n = 0; n < 8; n++) {
            const float p0 = __expf(sa[n][0] - m0);
            const float p1 = __expf(sa[n][1] - m0);
            const float p2 = __expf(sa[n][2] - m1);
            const float p3 = __expf(sa[n][3] - m1);
            s0 += p0 + p1; s1 += p2 + p3;
            *(float2*)&Psm[prow * PP + n * 8 + 2 * tg] =
                make_float2(tf32r(p0), tf32r(p1));
            *(float2*)&Psm[(prow + 8) * PP + n * 8 + 2 * tg] =
                make_float2(tf32r(p2), tf32r(p3));
            o[n][0] *= c0; o[n][1] *= c0; o[n][2] *= c1; o[n][3] *= c1;
        }
        s0 += __shfl_xor_sync(0xffffffffu, s0, 1);
        s0 += __shfl_xor_sync(0xffffffffu, s0, 2);
        s1 += __shfl_xor_sync(0xffffffffu, s1, 1);
        s1 += __shfl_xor_sync(0xffffffffu, s1, 2);
        l0 = l0 * c0 + s0;
        l1 = l1 * c1 + s1;
        __syncwarp();   // P rows warp-private: warp-local STS->LDS ordering

        // ---- O += P @ V ----
        const float* vs = Vsm[s];
        #pragma unroll
        for (int kf = 0; kf < 8; kf++) {
            const float* ap = Psm + prow * PP + kf * 8 + tg;
            const uint32_t a0 = __float_as_uint(ap[0]);
            const uint32_t a1 = __float_as_uint(ap[8 * PP]);
            const uint32_t a2 = __float_as_uint(ap[4]);
            const uint32_t a3 = __float_as_uint(ap[8 * PP + 4]);
            #pragma unroll
            for (int n = 0; n < 8; n++) {
                const float* bp = vs + (kf * 8 + tg) * VP + n * 8 + gID;
                mma_tf32(o[n][0], o[n][1], o[n][2], o[n][3],
                         a0, a1, a2, a3,
                         __float_as_uint(bp[0]), __float_as_uint(bp[4 * VP]));
            }
        }
    }

    // epilogue: normalize and store (rounded: consumed by out-proj mma)
    const float inv0 = 1.f / l0, inv1 = 1.f / l1;
    const size_t grow = (size_t)(bb * S + qbase + gID);
    #pragma unroll
    for (int n = 0; n < 8; n++) {
        const int col = h * DH + n * 8 + 2 * tg;
        *(float2*)&ctx[grow * INNER + col] =
            make_float2(tf32r(o[n][0] * inv0), tf32r(o[n][1] * inv0));
        *(float2*)&ctx[(grow + 8) * INNER + col] =
            make_float2(tf32r(o[n][2] * inv1), tf32r(o[n][3] * inv1));
    }
}

// ---------------------------------------------------------------------------
extern "C" void kernel_launch(void* const* d_in, const int* in_sizes, int n_in,
                              void* d_out, int out_size)
{
    const float* x        = (const float*)d_in[0];
    const float* ln_gamma = (const float*)d_in[1];
    const float* ln_beta  = (const float*)d_in[2];
    const float* w_qkv    = (const float*)d_in[3];
    const float* w_out    = (const float*)d_in[4];
    const float* b_out    = (const float*)d_in[5];
    float* out = (float*)d_out;

    void* sp = nullptr;
    cudaGetSymbolAddress(&sp, g_scratch);
    float* xn   = (float*)sp;
    float* qkv  = xn + (size_t)ROWS * D;
    float* ctx  = qkv + (size_t)ROWS * D3;
    float* wq_r = ctx + (size_t)ROWS * D;
    float* wo_r = wq_r + (size_t)D * D3;

    cudaFuncSetAttribute(gemm_kernel, cudaFuncAttributeMaxDynamicSharedMemorySize, GEMM_SMEM);
    cudaFuncSetAttribute(attn_kernel, cudaFuncAttributeMaxDynamicSharedMemorySize, ATTN_SMEM);

    // round weights to tf32 (unbiased rna)
    round_kernel<<<(D * D3 / 4 + 255) / 256, 256>>>(w_qkv, wq_r, D * D3 / 4);
    round_kernel<<<(D * D / 4 + 255) / 256, 256>>>(w_out, wo_r, D * D / 4);

    // 1. LayerNorm (tf32-rounded output)
    ln_kernel<<<ROWS, 256>>>(x, ln_gamma, ln_beta, xn);

    // 2. QKV projection (tensor cores, tf32-rounded output)
    gemm_kernel<<<dim3(D3 / 128, ROWS / 128), 256, GEMM_SMEM>>>(
        xn, wq_r, nullptr, qkv, D3, 1);

    // 3. Flash attention (tensor cores)
    attn_kernel<<<dim3(S / 256, HEADS, B), 512, ATTN_SMEM>>>(qkv, ctx);

    // 4. Output projection + bias (tensor cores, full fp32 out)
    gemm_kernel<<<dim3(D / 128, ROWS / 128), 256, GEMM_SMEM>>>(
        ctx, wo_r, b_out, out, D, 0);
}

// round 5
// speedup vs baseline: 1.1470x; 1.1470x over previous
#include <cuda_runtime.h>
#include <cstdint>
#include <math.h>

// Problem constants
#define B       2
#define S       2048
#define D       1024
#define HEADS   16
#define DH      64
#define INNER   1024
#define D3      3072
#define ROWS    4096
#define ATTN_SCALE 0.125f
#define LN_EPS  1e-5f

// Scratch: xn | qkv | ctx | w_qkv rounded | w_out rounded
__device__ float g_scratch[(size_t)ROWS * D + (size_t)ROWS * D3 + (size_t)ROWS * D
                           + (size_t)D * D3 + (size_t)D * D];

// ---------------------------------------------------------------------------
// Helpers
// ---------------------------------------------------------------------------
__device__ __forceinline__ uint32_t smem_u32(const void* p) {
    uint32_t a;
    asm("{ .reg .u64 t; cvta.to.shared.u64 t, %1; cvt.u32.u64 %0, t; }" : "=r"(a) : "l"(p));
    return a;
}
__device__ __forceinline__ float tf32r(float x) {
    uint32_t o;
    asm("cvt.rna.tf32.f32 %0, %1;" : "=r"(o) : "f"(x));
    return __uint_as_float(o);
}

#define CP_ASYNC16(dst, src) \
    asm volatile("cp.async.cg.shared.global [%0], [%1], 16;" :: "r"(dst), "l"(src))
#define CP_COMMIT()  asm volatile("cp.async.commit_group;" ::: "memory")
#define CP_WAIT1()   asm volatile("cp.async.wait_group 1;" ::: "memory")
#define CP_WAIT0()   asm volatile("cp.async.wait_group 0;" ::: "memory")

__device__ __forceinline__ void mma_tf32(
    float& d0, float& d1, float& d2, float& d3,
    uint32_t a0, uint32_t a1, uint32_t a2, uint32_t a3,
    uint32_t b0, uint32_t b1)
{
    asm volatile(
        "mma.sync.aligned.m16n8k8.row.col.f32.tf32.tf32.f32 "
        "{%0,%1,%2,%3}, {%4,%5,%6,%7}, {%8,%9}, {%0,%1,%2,%3};"
        : "+f"(d0), "+f"(d1), "+f"(d2), "+f"(d3)
        : "r"(a0), "r"(a1), "r"(a2), "r"(a3), "r"(b0), "r"(b1));
}

// ---------------------------------------------------------------------------
// LayerNorm (output rounded to tf32)
// ---------------------------------------------------------------------------
__global__ __launch_bounds__(256) void ln_kernel(
    const float* __restrict__ x, const float* __restrict__ gamma,
    const float* __restrict__ beta, float* __restrict__ y)
{
    const int row = blockIdx.x;
    const int t = threadIdx.x;
    const float4* xp = (const float4*)(x + (size_t)row * D);
    float4 v = xp[t];
    float s  = v.x + v.y + v.z + v.w;
    float ss = v.x * v.x + v.y * v.y + v.z * v.z + v.w * v.w;
    #pragma unroll
    for (int off = 16; off > 0; off >>= 1) {
        s  += __shfl_down_sync(0xffffffffu, s,  off);
        ss += __shfl_down_sync(0xffffffffu, ss, off);
    }
    __shared__ float sh_s[8], sh_ss[8];
    const int w = t >> 5, lane = t & 31;
    if (lane == 0) { sh_s[w] = s; sh_ss[w] = ss; }
    __syncthreads();
    __shared__ float mu_sh, rstd_sh;
    if (t == 0) {
        float S0 = 0.f, SS0 = 0.f;
        #pragma unroll
        for (int i = 0; i < 8; i++) { S0 += sh_s[i]; SS0 += sh_ss[i]; }
        const float mu  = S0 * (1.0f / D);
        const float var = SS0 * (1.0f / D) - mu * mu;
        mu_sh = mu;
        rstd_sh = rsqrtf(var + LN_EPS);
    }
    __syncthreads();
    const float mu = mu_sh, rstd = rstd_sh;
    float4 g  = ((const float4*)gamma)[t];
    float4 bb = ((const float4*)beta)[t];
    float4 o;
    o.x = tf32r((v.x - mu) * rstd * g.x + bb.x);
    o.y = tf32r((v.y - mu) * rstd * g.y + bb.y);
    o.z = tf32r((v.z - mu) * rstd * g.z + bb.z);
    o.w = tf32r((v.w - mu) * rstd * g.w + bb.w);
    ((float4*)(y + (size_t)row * D))[t] = o;
}

// ---------------------------------------------------------------------------
// Round a weight array to tf32 (rna)
// ---------------------------------------------------------------------------
__global__ __launch_bounds__(256) void round_kernel(
    const float* __restrict__ src, float* __restrict__ dst, int n4)
{
    int i = blockIdx.x * 256 + threadIdx.x;
    if (i < n4) {
        float4 v = ((const float4*)src)[i];
        v.x = tf32r(v.x); v.y = tf32r(v.y); v.z = tf32r(v.z); v.w = tf32r(v.w);
        ((float4*)dst)[i] = v;
    }
}

// ---------------------------------------------------------------------------
// TF32 mma.sync GEMM: C[M,N] = A[M,K=1024] @ W[K,N] (+bias)
// 128x128 tile, BK=32, 256 threads (8 warps, warp-tile 32x64), cp.async x2.
// (R3-exact version: fastest measured)
// ---------------------------------------------------------------------------
#define GA_P 36
#define GB_P 136
#define GA_ST (128 * GA_P)
#define GB_ST (32 * GB_P)
#define GEMM_SMEM ((2 * GA_ST + 2 * GB_ST) * 4)   // 71680 B

__global__ __launch_bounds__(256, 2) void gemm_kernel(
    const float* __restrict__ A, const float* __restrict__ W,
    const float* __restrict__ bias, float* __restrict__ C,
    int N, int round_out)
{
    extern __shared__ float sm[];
    const int tid = threadIdx.x;
    const int wid = tid >> 5, lane = tid & 31;
    const int gID = lane >> 2, tg = lane & 3;
    const int bm = blockIdx.y * 128, bn = blockIdx.x * 128;
    const int wm = (wid & 3) * 32, wn = (wid >> 2) * 64;

    float* Asm[2] = { sm, sm + GA_ST };
    float* Bsm[2] = { sm + 2 * GA_ST, sm + 2 * GA_ST + GB_ST };
    const uint32_t aB[2] = { smem_u32(Asm[0]), smem_u32(Asm[1]) };
    const uint32_t bB[2] = { smem_u32(Bsm[0]), smem_u32(Bsm[1]) };

    float acc[2][8][4];
    #pragma unroll
    for (int im = 0; im < 2; im++)
        #pragma unroll
        for (int n = 0; n < 8; n++)
            #pragma unroll
            for (int j = 0; j < 4; j++) acc[im][n][j] = 0.f;

    // prologue: chunks 0,1
    #pragma unroll
    for (int pi = 0; pi < 2; pi++) {
        const int k0 = pi * 32;
        #pragma unroll
        for (int j = 0; j < 4; j++) {
            const int idx = tid + j * 256;
            const int r = idx >> 3, c = idx & 7;
            CP_ASYNC16(aB[pi] + (uint32_t)(r * GA_P + c * 4) * 4u,
                       A + (size_t)(bm + r) * D + k0 + c * 4);
        }
        #pragma unroll
        for (int j = 0; j < 4; j++) {
            const int idx = tid + j * 256;
            const int r = idx >> 5, c = idx & 31;
            CP_ASYNC16(bB[pi] + (uint32_t)(r * GB_P + c * 4) * 4u,
                       W + (size_t)(k0 + r) * N + bn + c * 4);
        }
        CP_COMMIT();
    }

    for (int i = 0; i < 32; i++) {
        const int s = i & 1;
        if (i < 31) { CP_WAIT1(); } else { CP_WAIT0(); }
        __syncthreads();
        const float* as = Asm[s];
        const float* bs = Bsm[s];
        #pragma unroll
        for (int ks = 0; ks < 4; ks++) {
            const int k = ks * 8;
            uint32_t af[2][4];
            #pragma unroll
            for (int im = 0; im < 2; im++) {
                const float* p = as + (wm + im * 16 + gID) * GA_P + k + tg;
                af[im][0] = __float_as_uint(p[0]);
                af[im][1] = __float_as_uint(p[8 * GA_P]);
                af[im][2] = __float_as_uint(p[4]);
                af[im][3] = __float_as_uint(p[8 * GA_P + 4]);
            }
            #pragma unroll
            for (int n = 0; n < 8; n++) {
                const float* p = bs + (k + tg) * GB_P + wn + n * 8 + gID;
                const uint32_t b0 = __float_as_uint(p[0]);
                const uint32_t b1 = __float_as_uint(p[4 * GB_P]);
                #pragma unroll
                for (int im = 0; im < 2; im++)
                    mma_tf32(acc[im][n][0], acc[im][n][1], acc[im][n][2], acc[im][n][3],
                             af[im][0], af[im][1], af[im][2], af[im][3], b0, b1);
            }
        }
        __syncthreads();
        if (i + 2 < 32) {
            const int k0 = (i + 2) * 32;
            #pragma unroll
            for (int j = 0; j < 4; j++) {
                const int idx = tid + j * 256;
                const int r = idx >> 3, c = idx & 7;
                CP_ASYNC16(aB[s] + (uint32_t)(r * GA_P + c * 4) * 4u,
                           A + (size_t)(bm + r) * D + k0 + c * 4);
            }
            #pragma unroll
            for (int j = 0; j < 4; j++) {
                const int idx = tid + j * 256;
                const int r = idx >> 5, c = idx & 31;
                CP_ASYNC16(bB[s] + (uint32_t)(r * GB_P + c * 4) * 4u,
                           W + (size_t)(k0 + r) * N + bn + c * 4);
            }
            CP_COMMIT();
        }
    }

    // epilogue
    #pragma unroll
    for (int im = 0; im < 2; im++) {
        const int r0 = bm + wm + im * 16 + gID;
        #pragma unroll
        for (int n = 0; n < 8; n++) {
            const int col = bn + wn + n * 8 + 2 * tg;
            float v0 = acc[im][n][0], v1 = acc[im][n][1];
            float v2 = acc[im][n][2], v3 = acc[im][n][3];
            if (bias) {
                const float b0 = bias[col], b1 = bias[col + 1];
                v0 += b0; v1 += b1; v2 += b0; v3 += b1;
            }
            if (round_out) {
                v0 = tf32r(v0); v1 = tf32r(v1); v2 = tf32r(v2); v3 = tf32r(v3);
            }
            *(float2*)&C[(size_t)r0 * N + col]       = make_float2(v0, v1);
            *(float2*)&C[(size_t)(r0 + 8) * N + col] = make_float2(v2, v3);
        }
    }
}

// ---------------------------------------------------------------------------
// TF32 mma.sync flash attention — P stays in registers.
// k-slot relabeling: PV mma slot tg <-> key 2tg, slot tg+4 <-> key 2tg+1,
// so the S accumulator IS the PV A-fragment; V rows read as (2tg, 2tg+1).
// Block: 256 threads / 8 warps, 128 queries (16/warp), 64-key tiles, 2-stage.
// grid (S/128, HEADS, B)
// ---------------------------------------------------------------------------
#define KP 68
#define VP 68
#define K_ST (64 * KP)
#define V_ST (64 * VP)
#define ATTN_SMEM ((2 * K_ST + 2 * V_ST) * 4)   // 69632 B

__global__ __launch_bounds__(256, 2) void attn_kernel(
    const float* __restrict__ qkv, float* __restrict__ ctx)
{
    extern __shared__ float sm[];
    float* Ksm[2] = { sm, sm + K_ST };
    float* Vsm[2] = { sm + 2 * K_ST, sm + 2 * K_ST + V_ST };
    const uint32_t kB[2] = { smem_u32(Ksm[0]), smem_u32(Ksm[1]) };
    const uint32_t vB[2] = { smem_u32(Vsm[0]), smem_u32(Vsm[1]) };

    const int tid = threadIdx.x;
    const int wid = tid >> 5, lane = tid & 31;
    const int gID = lane >> 2, tg = lane & 3;
    const int h = blockIdx.y, bb = blockIdx.z;
    const int qbase = blockIdx.x * 128 + wid * 16;

    const float* qp = qkv + (size_t)(bb * S + qbase) * D3 + h * DH;
    const float* kbase = qkv + (size_t)bb * S * D3 + INNER + h * DH;
    const float* vbase = kbase + INNER;

    // Q fragments in registers (x0.125 exact power of 2, stays tf32)
    uint32_t qf[8][4];
    #pragma unroll
    for (int kf = 0; kf < 8; kf++) {
        const int k = kf * 8;
        qf[kf][0] = __float_as_uint(qp[(size_t)gID * D3 + k + tg] * ATTN_SCALE);
        qf[kf][1] = __float_as_uint(qp[(size_t)(gID + 8) * D3 + k + tg] * ATTN_SCALE);
        qf[kf][2] = __float_as_uint(qp[(size_t)gID * D3 + k + tg + 4] * ATTN_SCALE);
        qf[kf][3] = __float_as_uint(qp[(size_t)(gID + 8) * D3 + k + tg + 4] * ATTN_SCALE);
    }

    float o[8][4];
    #pragma unroll
    for (int n = 0; n < 8; n++)
        #pragma unroll
        for (int j = 0; j < 4; j++) o[n][j] = 0.f;
    float m0 = -1e30f, m1 = -1e30f, l0 = 0.f, l1 = 0.f;

    // prologue: tiles 0,1
    #pragma unroll
    for (int pi = 0; pi < 2; pi++) {
        const int r0 = pi * 64;
        #pragma unroll
        for (int j = 0; j < 4; j++) {
            const int idx = tid + j * 256;
            const int r = idx >> 4, c = (idx & 15) * 4;
            CP_ASYNC16(kB[pi] + (uint32_t)(r * KP + c) * 4u,
                       kbase + (size_t)(r0 + r) * D3 + c);
            CP_ASYNC16(vB[pi] + (uint32_t)(r * VP + c) * 4u,
                       vbase + (size_t)(r0 + r) * D3 + c);
        }
        CP_COMMIT();
    }

    for (int i = 0; i < 32; i++) {
        const int s = i & 1;
        if (i < 31) { CP_WAIT1(); } else { CP_WAIT0(); }
        __syncthreads();

        // ---- S = Q @ K^T ----
        float sa[8][4];
        #pragma unroll
        for (int n = 0; n < 8; n++)
            #pragma unroll
            for (int j = 0; j < 4; j++) sa[n][j] = 0.f;
        const float* ks = Ksm[s];
        #pragma unroll
        for (int kf = 0; kf < 8; kf++) {
            const int k = kf * 8;
            #pragma unroll
            for (int n = 0; n < 8; n++) {
                const float* p = ks + (n * 8 + gID) * KP + k + tg;
                mma_tf32(sa[n][0], sa[n][1], sa[n][2], sa[n][3],
                         qf[kf][0], qf[kf][1], qf[kf][2], qf[kf][3],
                         __float_as_uint(p[0]), __float_as_uint(p[4]));
            }
        }

        // ---- online softmax (P kept in registers, tf32-rounded in place) ----
        float rmax0 = sa[0][0], rmax1 = sa[0][2];
        #pragma unroll
        for (int n = 0; n < 8; n++) {
            rmax0 = fmaxf(rmax0, fmaxf(sa[n][0], sa[n][1]));
            rmax1 = fmaxf(rmax1, fmaxf(sa[n][2], sa[n][3]));
        }
        rmax0 = fmaxf(rmax0, __shfl_xor_sync(0xffffffffu, rmax0, 1));
        rmax0 = fmaxf(rmax0, __shfl_xor_sync(0xffffffffu, rmax0, 2));
        rmax1 = fmaxf(rmax1, __shfl_xor_sync(0xffffffffu, rmax1, 1));
        rmax1 = fmaxf(rmax1, __shfl_xor_sync(0xffffffffu, rmax1, 2));
        const float nm0 = fmaxf(m0, rmax0), nm1 = fmaxf(m1, rmax1);
        const float c0 = __expf(m0 - nm0), c1 = __expf(m1 - nm1);
        m0 = nm0; m1 = nm1;
        float s0 = 0.f, s1 = 0.f;
        #pragma unroll
        for (int n = 0; n < 8; n++) {
            const float p0 = __expf(sa[n][0] - m0);
            const float p1 = __expf(sa[n][1] - m0);
            const float p2 = __expf(sa[n][2] - m1);
            const float p3 = __expf(sa[n][3] - m1);
            s0 += p0 + p1; s1 += p2 + p3;
            sa[n][0] = tf32r(p0); sa[n][1] = tf32r(p1);
            sa[n][2] = tf32r(p2); sa[n][3] = tf32r(p3);
            o[n][0] *= c0; o[n][1] *= c0; o[n][2] *= c1; o[n][3] *= c1;
        }
        s0 += __shfl_xor_sync(0xffffffffu, s0, 1);
        s0 += __shfl_xor_sync(0xffffffffu, s0, 2);
        s1 += __shfl_xor_sync(0xffffffffu, s1, 1);
        s1 += __shfl_xor_sync(0xffffffffu, s1, 2);
        l0 = l0 * c0 + s0;
        l1 = l1 * c1 + s1;

        // ---- O += P @ V ----
        // A frag from sa directly: a0=(r0,key 2tg)=sa[kf][0], a1=(r1,key 2tg)=sa[kf][2],
        // a2=(r0,key 2tg+1)=sa[kf][1], a3=(r1,key 2tg+1)=sa[kf][3].
        // B frag: b0=V[key kf*8+2tg][col], b1=V[key kf*8+2tg+1][col].
        const float* vs = Vsm[s];
        #pragma unroll
        for (int kf = 0; kf < 8; kf++) {
            const uint32_t a0 = __float_as_uint(sa[kf][0]);
            const uint32_t a1 = __float_as_uint(sa[kf][2]);
            const uint32_t a2 = __float_as_uint(sa[kf][1]);
            const uint32_t a3 = __float_as_uint(sa[kf][3]);
            #pragma unroll
            for (int n = 0; n < 8; n++) {
                const float* bp = vs + (kf * 8 + 2 * tg) * VP + n * 8 + gID;
                mma_tf32(o[n][0], o[n][1], o[n][2], o[n][3],
                         a0, a1, a2, a3,
                         __float_as_uint(bp[0]), __float_as_uint(bp[VP]));
            }
        }
        __syncthreads();

        if (i + 2 < 32) {
            const int r0 = (i + 2) * 64;
            #pragma unroll
            for (int j = 0; j < 4; j++) {
                const int idx = tid + j * 256;
                const int r = idx >> 4, c = (idx & 15) * 4;
                CP_ASYNC16(kB[s] + (uint32_t)(r * KP + c) * 4u,
                           kbase + (size_t)(r0 + r) * D3 + c);
                CP_ASYNC16(vB[s] + (uint32_t)(r * VP + c) * 4u,
                           vbase + (size_t)(r0 + r) * D3 + c);
            }
            CP_COMMIT();
        }
    }

    // epilogue: normalize and store (rounded: consumed by out-proj mma)
    const float inv0 = 1.f / l0, inv1 = 1.f / l1;
    const size_t grow = (size_t)(bb * S + qbase + gID);
    #pragma unroll
    for (int n = 0; n < 8; n++) {
        const int col = h * DH + n * 8 + 2 * tg;
        *(float2*)&ctx[grow * INNER + col] =
            make_float2(tf32r(o[n][0] * inv0), tf32r(o[n][1] * inv0));
        *(float2*)&ctx[(grow + 8) * INNER + col] =
            make_float2(tf32r(o[n][2] * inv1), tf32r(o[n][3] * inv1));
    }
}

// ---------------------------------------------------------------------------
extern "C" void kernel_launch(void* const* d_in, const int* in_sizes, int n_in,
                              void* d_out, int out_size)
{
    const float* x        = (const float*)d_in[0];
    const float* ln_gamma = (const float*)d_in[1];
    const float* ln_beta  = (const float*)d_in[2];
    const float* w_qkv    = (const float*)d_in[3];
    const float* w_out    = (const float*)d_in[4];
    const float* b_out    = (const float*)d_in[5];
    float* out = (float*)d_out;

    void* sp = nullptr;
    cudaGetSymbolAddress(&sp, g_scratch);
    float* xn   = (float*)sp;
    float* qkv  = xn + (size_t)ROWS * D;
    float* ctx  = qkv + (size_t)ROWS * D3;
    float* wq_r = ctx + (size_t)ROWS * D;
    float* wo_r = wq_r + (size_t)D * D3;

    cudaFuncSetAttribute(gemm_kernel, cudaFuncAttributeMaxDynamicSharedMemorySize, GEMM_SMEM);
    cudaFuncSetAttribute(attn_kernel, cudaFuncAttributeMaxDynamicSharedMemorySize, ATTN_SMEM);

    // round weights to tf32 (unbiased rna)
    round_kernel<<<(D * D3 / 4 + 255) / 256, 256>>>(w_qkv, wq_r, D * D3 / 4);
    round_kernel<<<(D * D / 4 + 255) / 256, 256>>>(w_out, wo_r, D * D / 4);

    // 1. LayerNorm (tf32-rounded output)
    ln_kernel<<<ROWS, 256>>>(x, ln_gamma, ln_beta, xn);

    // 2. QKV projection (tensor cores, tf32-rounded output)
    gemm_kernel<<<dim3(D3 / 128, ROWS / 128), 256, GEMM_SMEM>>>(
        xn, wq_r, nullptr, qkv, D3, 1);

    // 3. Flash attention (tensor cores, register-resident P)
    attn_kernel<<<dim3(S / 128, HEADS, B), 256, ATTN_SMEM>>>(qkv, ctx);

    // 4. Output projection + bias (tensor cores, full fp32 out)
    gemm_kernel<<<dim3(D / 128, ROWS / 128), 256, GEMM_SMEM>>>(
        ctx, wo_r, b_out, out, D, 0);
}

// round 7
// speedup vs baseline: 1.1934x; 1.0404x over previous
#include <cuda_runtime.h>
#include <cstdint>
#include <math.h>

// Problem constants
#define B       2
#define S       2048
#define D       1024
#define HEADS   16
#define DH      64
#define INNER   1024
#define D3      3072
#define ROWS    4096
#define ATTN_SCALE 0.125f
#define LN_EPS  1e-5f

// Scratch: xn | qkv | ctx | w_qkv^T rounded | w_out^T rounded
__device__ float g_scratch[(size_t)ROWS * D + (size_t)ROWS * D3 + (size_t)ROWS * D
                           + (size_t)D * D3 + (size_t)D * D];

// ---------------------------------------------------------------------------
// Helpers
// ---------------------------------------------------------------------------
__device__ __forceinline__ uint32_t smem_u32(const void* p) {
    uint32_t a;
    asm("{ .reg .u64 t; cvta.to.shared.u64 t, %1; cvt.u32.u64 %0, t; }" : "=r"(a) : "l"(p));
    return a;
}
__device__ __forceinline__ float tf32r(float x) {
    uint32_t o;
    asm("cvt.rna.tf32.f32 %0, %1;" : "=r"(o) : "f"(x));
    return __uint_as_float(o);
}

#define CP_ASYNC16(dst, src) \
    asm volatile("cp.async.cg.shared.global [%0], [%1], 16;" :: "r"(dst), "l"(src))
#define CP_COMMIT()  asm volatile("cp.async.commit_group;" ::: "memory")
#define CP_WAIT1()   asm volatile("cp.async.wait_group 1;" ::: "memory")
#define CP_WAIT0()   asm volatile("cp.async.wait_group 0;" ::: "memory")

__device__ __forceinline__ void mma_tf32(
    float& d0, float& d1, float& d2, float& d3,
    uint32_t a0, uint32_t a1, uint32_t a2, uint32_t a3,
    uint32_t b0, uint32_t b1)
{
    asm volatile(
        "mma.sync.aligned.m16n8k8.row.col.f32.tf32.tf32.f32 "
        "{%0,%1,%2,%3}, {%4,%5,%6,%7}, {%8,%9}, {%0,%1,%2,%3};"
        : "+f"(d0), "+f"(d1), "+f"(d2), "+f"(d3)
        : "r"(a0), "r"(a1), "r"(a2), "r"(a3), "r"(b0), "r"(b1));
}
#define U(x) __float_as_uint(x)

// ---------------------------------------------------------------------------
// LayerNorm (output rounded to tf32)
// ---------------------------------------------------------------------------
__global__ __launch_bounds__(256) void ln_kernel(
    const float* __restrict__ x, const float* __restrict__ gamma,
    const float* __restrict__ beta, float* __restrict__ y)
{
    const int row = blockIdx.x;
    const int t = threadIdx.x;
    const float4* xp = (const float4*)(x + (size_t)row * D);
    float4 v = xp[t];
    float s  = v.x + v.y + v.z + v.w;
    float ss = v.x * v.x + v.y * v.y + v.z * v.z + v.w * v.w;
    #pragma unroll
    for (int off = 16; off > 0; off >>= 1) {
        s  += __shfl_down_sync(0xffffffffu, s,  off);
        ss += __shfl_down_sync(0xffffffffu, ss, off);
    }
    __shared__ float sh_s[8], sh_ss[8];
    const int w = t >> 5, lane = t & 31;
    if (lane == 0) { sh_s[w] = s; sh_ss[w] = ss; }
    __syncthreads();
    __shared__ float mu_sh, rstd_sh;
    if (t == 0) {
        float S0 = 0.f, SS0 = 0.f;
        #pragma unroll
        for (int i = 0; i < 8; i++) { S0 += sh_s[i]; SS0 += sh_ss[i]; }
        const float mu  = S0 * (1.0f / D);
        const float var = SS0 * (1.0f / D) - mu * mu;
        mu_sh = mu;
        rstd_sh = rsqrtf(var + LN_EPS);
    }
    __syncthreads();
    const float mu = mu_sh, rstd = rstd_sh;
    float4 g  = ((const float4*)gamma)[t];
    float4 bb = ((const float4*)beta)[t];
    float4 o;
    o.x = tf32r((v.x - mu) * rstd * g.x + bb.x);
    o.y = tf32r((v.y - mu) * rstd * g.y + bb.y);
    o.z = tf32r((v.z - mu) * rstd * g.z + bb.z);
    o.w = tf32r((v.w - mu) * rstd * g.w + bb.w);
    ((float4*)(y + (size_t)row * D))[t] = o;
}

// ---------------------------------------------------------------------------
// Transpose + round: src W[K_][C_] -> dst WT[C_][K_], tf32-rounded.
// grid (C_/32, K_/32), block (32, 8)
// ---------------------------------------------------------------------------
__global__ __launch_bounds__(256) void transpose_round_kernel(
    const float* __restrict__ src, float* __restrict__ dst, int K_, int C_)
{
    __shared__ float tile[32][33];
    const int c0 = blockIdx.x * 32, k0 = blockIdx.y * 32;
    const int tx = threadIdx.x, ty = threadIdx.y;
    #pragma unroll
    for (int j = 0; j < 32; j += 8)
        tile[ty + j][tx] = src[(size_t)(k0 + ty + j) * C_ + c0 + tx];
    __syncthreads();
    #pragma unroll
    for (int j = 0; j < 32; j += 8)
        dst[(size_t)(c0 + ty + j) * K_ + k0 + tx] = tf32r(tile[tx][ty + j]);
}

// ---------------------------------------------------------------------------
// TF32 mma.sync GEMM: C[M,N] = A[M,K=1024] @ WT[N,K]^T (+bias)
// 128x128 tile, BK=32, 256 threads (8 warps, warp-tile 32x64), cp.async x2.
// k-permuted fragments: all smem fragment loads are LDS.128.
// Pitch 48 (=16 mod 32): per-phase bank-group = 4*gID+tg, conflict-free.
// ---------------------------------------------------------------------------
#define GA_P 48
#define GB_P 48
#define GA_ST (128 * GA_P)
#define GB_ST (128 * GB_P)
#define GEMM_SMEM ((2 * GA_ST + 2 * GB_ST) * 4)   // 98304 B

__global__ __launch_bounds__(256, 2) void gemm_kernel(
    const float* __restrict__ A, const float* __restrict__ WT,
    const float* __restrict__ bias, float* __restrict__ C,
    int N, int round_out)
{
    extern __shared__ float sm[];
    const int tid = threadIdx.x;
    const int wid = tid >> 5, lane = tid & 31;
    const int gID = lane >> 2, tg = lane & 3;
    const int bm = blockIdx.y * 128, bn = blockIdx.x * 128;
    const int wm = (wid & 3) * 32, wn = (wid >> 2) * 64;

    float* Asm[2] = { sm, sm + GA_ST };
    float* Bsm[2] = { sm + 2 * GA_ST, sm + 2 * GA_ST + GB_ST };
    const uint32_t aB[2] = { smem_u32(Asm[0]), smem_u32(Asm[1]) };
    const uint32_t bB[2] = { smem_u32(Bsm[0]), smem_u32(Bsm[1]) };

    float acc[2][8][4];
    #pragma unroll
    for (int im = 0; im < 2; im++)
        #pragma unroll
        for (int n = 0; n < 8; n++)
            #pragma unroll
            for (int j = 0; j < 4; j++) acc[im][n][j] = 0.f;

    // prologue: chunks 0,1   (A rows & WT rows both K-contiguous)
    #pragma unroll
    for (int pi = 0; pi < 2; pi++) {
        const int k0 = pi * 32;
        #pragma unroll
        for (int j = 0; j < 4; j++) {
            const int idx = tid + j * 256;
            const int r = idx >> 3, c = idx & 7;
            CP_ASYNC16(aB[pi] + (uint32_t)(r * GA_P + c * 4) * 4u,
                       A + (size_t)(bm + r) * D + k0 + c * 4);
            CP_ASYNC16(bB[pi] + (uint32_t)(r * GB_P + c * 4) * 4u,
                       WT + (size_t)(bn + r) * D + k0 + c * 4);
        }
        CP_COMMIT();
    }

    for (int i = 0; i < 32; i++) {
        const int s = i & 1;
        if (i < 31) { CP_WAIT1(); } else { CP_WAIT0(); }
        __syncthreads();
        const float* as = Asm[s];
        const float* bs = Bsm[s];
        #pragma unroll
        for (int kg = 0; kg < 2; kg++) {
            // A fragments: one LDS.128 per (im, row-half)
            float4 a4[2][2];
            #pragma unroll
            for (int im = 0; im < 2; im++) {
                a4[im][0] = *(const float4*)(as + (wm + im * 16 + gID) * GA_P + kg * 16 + 4 * tg);
                a4[im][1] = *(const float4*)(as + (wm + im * 16 + gID + 8) * GA_P + kg * 16 + 4 * tg);
            }
            #pragma unroll
            for (int n = 0; n < 8; n++) {
                const float4 bv = *(const float4*)(bs + (wn + n * 8 + gID) * GB_P + kg * 16 + 4 * tg);
                #pragma unroll
                for (int im = 0; im < 2; im++) {
                    mma_tf32(acc[im][n][0], acc[im][n][1], acc[im][n][2], acc[im][n][3],
                             U(a4[im][0].x), U(a4[im][1].x), U(a4[im][0].y), U(a4[im][1].y),
                             U(bv.x), U(bv.y));
                    mma_tf32(acc[im][n][0], acc[im][n][1], acc[im][n][2], acc[im][n][3],
                             U(a4[im][0].z), U(a4[im][1].z), U(a4[im][0].w), U(a4[im][1].w),
                             U(bv.z), U(bv.w));
                }
            }
        }
        __syncthreads();
        if (i + 2 < 32) {
            const int k0 = (i + 2) * 32;
            #pragma unroll
            for (int j = 0; j < 4; j++) {
                const int idx = tid + j * 256;
                const int r = idx >> 3, c = idx & 7;
                CP_ASYNC16(aB[s] + (uint32_t)(r * GA_P + c * 4) * 4u,
                           A + (size_t)(bm + r) * D + k0 + c * 4);
                CP_ASYNC16(bB[s] + (uint32_t)(r * GB_P + c * 4) * 4u,
                           WT + (size_t)(bn + r) * D + k0 + c * 4);
            }
            CP_COMMIT();
        }
    }

    // epilogue (acc layout: d0,d1 = row gID cols 2tg,2tg+1; d2,d3 = row gID+8)
    #pragma unroll
    for (int im = 0; im < 2; im++) {
        const int r0 = bm + wm + im * 16 + gID;
        #pragma unroll
        for (int n = 0; n < 8; n++) {
            const int col = bn + wn + n * 8 + 2 * tg;
            float v0 = acc[im][n][0], v1 = acc[im][n][1];
            float v2 = acc[im][n][2], v3 = acc[im][n][3];
            if (bias) {
                const float b0 = bias[col], b1 = bias[col + 1];
                v0 += b0; v1 += b1; v2 += b0; v3 += b1;
            }
            if (round_out) {
                v0 = tf32r(v0); v1 = tf32r(v1); v2 = tf32r(v2); v3 = tf32r(v3);
            }
            *(float2*)&C[(size_t)r0 * N + col]       = make_float2(v0, v1);
            *(float2*)&C[(size_t)(r0 + 8) * N + col] = make_float2(v2, v3);
        }
    }
}

// ---------------------------------------------------------------------------
// TF32 mma.sync flash attention — register-resident P + d-permuted K frags.
// S-stage: d-axis permuted so K fragment loads are LDS.128 (pitch 80) and
// Q fragments are float4 gmem loads. PV-stage: R5 key-relabel trick.
// Block: 256 threads / 8 warps, 128 queries (16/warp), 64-key tiles, 2-stage.
// grid (S/128, HEADS, B)
// ---------------------------------------------------------------------------
#define KP 80
#define VP 68
#define K_ST (64 * KP)
#define V_ST (64 * VP)
#define ATTN_SMEM ((2 * K_ST + 2 * V_ST) * 4)   // 75776 B

__global__ __launch_bounds__(256, 2) void attn_kernel(
    const float* __restrict__ qkv, float* __restrict__ ctx)
{
    extern __shared__ float sm[];
    float* Ksm[2] = { sm, sm + K_ST };
    float* Vsm[2] = { sm + 2 * K_ST, sm + 2 * K_ST + V_ST };
    const uint32_t kB[2] = { smem_u32(Ksm[0]), smem_u32(Ksm[1]) };
    const uint32_t vB[2] = { smem_u32(Vsm[0]), smem_u32(Vsm[1]) };

    const int tid = threadIdx.x;
    const int wid = tid >> 5, lane = tid & 31;
    const int gID = lane >> 2, tg = lane & 3;
    const int h = blockIdx.y, bb = blockIdx.z;
    const int qbase = blockIdx.x * 128 + wid * 16;

    const float* qp = qkv + (size_t)(bb * S + qbase) * D3 + h * DH;
    const float* kbase = qkv + (size_t)bb * S * D3 + INNER + h * DH;
    const float* vbase = kbase + INNER;

    // Q fragments: d-permuted, float4 loads (x0.125 exact, stays tf32)
    float4 qf[4][2];
    #pragma unroll
    for (int kg = 0; kg < 4; kg++) {
        float4 v0 = *(const float4*)(qp + (size_t)gID * D3 + kg * 16 + 4 * tg);
        float4 v1 = *(const float4*)(qp + (size_t)(gID + 8) * D3 + kg * 16 + 4 * tg);
        v0.x *= ATTN_SCALE; v0.y *= ATTN_SCALE; v0.z *= ATTN_SCALE; v0.w *= ATTN_SCALE;
        v1.x *= ATTN_SCALE; v1.y *= ATTN_SCALE; v1.z *= ATTN_SCALE; v1.w *= ATTN_SCALE;
        qf[kg][0] = v0; qf[kg][1] = v1;
    }

    float o[8][4];
    #pragma unroll
    for (int n = 0; n < 8; n++)
        #pragma unroll
        for (int j = 0; j < 4; j++) o[n][j] = 0.f;
    float m0 = -1e30f, m1 = -1e30f, l0 = 0.f, l1 = 0.f;

    // prologue: tiles 0,1
    #pragma unroll
    for (int pi = 0; pi < 2; pi++) {
        const int r0 = pi * 64;
        #pragma unroll
        for (int j = 0; j < 4; j++) {
            const int idx = tid + j * 256;
            const int r = idx >> 4, c = (idx & 15) * 4;
            CP_ASYNC16(kB[pi] + (uint32_t)(r * KP + c) * 4u,
                       kbase + (size_t)(r0 + r) * D3 + c);
            CP_ASYNC16(vB[pi] + (uint32_t)(r * VP + c) * 4u,
                       vbase + (size_t)(r0 + r) * D3 + c);
        }
        CP_COMMIT();
    }

    for (int i = 0; i < 32; i++) {
        const int s = i & 1;
        if (i < 31) { CP_WAIT1(); } else { CP_WAIT0(); }
        __syncthreads();

        // ---- S = Q @ K^T  (d-permuted fragments) ----
        float sa[8][4];
        #pragma unroll
        for (int n = 0; n < 8; n++)
            #pragma unroll
            for (int j = 0; j < 4; j++) sa[n][j] = 0.f;
        const float* ks = Ksm[s];
        #pragma unroll
        for (int kg = 0; kg < 4; kg++) {
            #pragma unroll
            for (int n = 0; n < 8; n++) {
                const float4 kv = *(const float4*)(ks + (n * 8 + gID) * KP + kg * 16 + 4 * tg);
                mma_tf32(sa[n][0], sa[n][1], sa[n][2], sa[n][3],
                         U(qf[kg][0].x), U(qf[kg][1].x), U(qf[kg][0].y), U(qf[kg][1].y),
                         U(kv.x), U(kv.y));
                mma_tf32(sa[n][0], sa[n][1], sa[n][2], sa[n][3],
                         U(qf[kg][0].z), U(qf[kg][1].z), U(qf[kg][0].w), U(qf[kg][1].w),
                         U(kv.z), U(kv.w));
            }
        }

        // ---- online softmax (P in registers, tf32-rounded in place) ----
        float rmax0 = sa[0][0], rmax1 = sa[0][2];
        #pragma unroll
        for (int n = 0; n < 8; n++) {
            rmax0 = fmaxf(rmax0, fmaxf(sa[n][0], sa[n][1]));
            rmax1 = fmaxf(rmax1, fmaxf(sa[n][2], sa[n][3]));
        }
        rmax0 = fmaxf(rmax0, __shfl_xor_sync(0xffffffffu, rmax0, 1));
        rmax0 = fmaxf(rmax0, __shfl_xor_sync(0xffffffffu, rmax0, 2));
        rmax1 = fmaxf(rmax1, __shfl_xor_sync(0xffffffffu, rmax1, 1));
        rmax1 = fmaxf(rmax1, __shfl_xor_sync(0xffffffffu, rmax1, 2));
        const float nm0 = fmaxf(m0, rmax0), nm1 = fmaxf(m1, rmax1);
        const float c0 = __expf(m0 - nm0), c1 = __expf(m1 - nm1);
        m0 = nm0; m1 = nm1;
        float s0 = 0.f, s1 = 0.f;
        #pragma unroll
        for (int n = 0; n < 8; n++) {
            const float p0 = __expf(sa[n][0] - m0);
            const float p1 = __expf(sa[n][1] - m0);
            const float p2 = __expf(sa[n][2] - m1);
            const float p3 = __expf(sa[n][3] - m1);
            s0 += p0 + p1; s1 += p2 + p3;
            sa[n][0] = tf32r(p0); sa[n][1] = tf32r(p1);
            sa[n][2] = tf32r(p2); sa[n][3] = tf32r(p3);
            o[n][0] *= c0; o[n][1] *= c0; o[n][2] *= c1; o[n][3] *= c1;
        }
        s0 += __shfl_xor_sync(0xffffffffu, s0, 1);
        s0 += __shfl_xor_sync(0xffffffffu, s0, 2);
        s1 += __shfl_xor_sync(0xffffffffu, s1, 1);
        s1 += __shfl_xor_sync(0xffffffffu, s1, 2);
        l0 = l0 * c0 + s0;
        l1 = l1 * c1 + s1;

        // ---- O += P @ V  (key-relabel: S acc IS the A fragment) ----
        const float* vs = Vsm[s];
        #pragma unroll
        for (int kf = 0; kf < 8; kf++) {
            const uint32_t a0 = U(sa[kf][0]);
            const uint32_t a1 = U(sa[kf][2]);
            const uint32_t a2 = U(sa[kf][1]);
            const uint32_t a3 = U(sa[kf][3]);
            #pragma unroll
            for (int n = 0; n < 8; n++) {
                const float* bp = vs + (kf * 8 + 2 * tg) * VP + n * 8 + gID;
                mma_tf32(o[n][0], o[n][1], o[n][2], o[n][3],
                         a0, a1, a2, a3,
                         U(bp[0]), U(bp[VP]));
            }
        }
        __syncthreads();

        if (i + 2 < 32) {
            const int r0 = (i + 2) * 64;
            #pragma unroll
            for (int j = 0; j < 4; j++) {
                const int idx = tid + j * 256;
                const int r = idx >> 4, c = (idx & 15) * 4;
                CP_ASYNC16(kB[s] + (uint32_t)(r * KP + c) * 4u,
                           kbase + (size_t)(r0 + r) * D3 + c);
                CP_ASYNC16(vB[s] + (uint32_t)(r * VP + c) * 4u,
                           vbase + (size_t)(r0 + r) * D3 + c);
            }
            CP_COMMIT();
        }
    }

    // epilogue: normalize and store (rounded: consumed by out-proj mma)
    const float inv0 = 1.f / l0, inv1 = 1.f / l1;
    const size_t grow = (size_t)(bb * S + qbase + gID);
    #pragma unroll
    for (int n = 0; n < 8; n++) {
        const int col = h * DH + n * 8 + 2 * tg;
        *(float2*)&ctx[grow * INNER + col] =
            make_float2(tf32r(o[n][0] * inv0), tf32r(o[n][1] * inv0));
        *(float2*)&ctx[(grow + 8) * INNER + col] =
            make_float2(tf32r(o[n][2] * inv1), tf32r(o[n][3] * inv1));
    }
}

// ---------------------------------------------------------------------------
extern "C" void kernel_launch(void* const* d_in, const int* in_sizes, int n_in,
                              void* d_out, int out_size)
{
    const float* x        = (const float*)d_in[0];
    const float* ln_gamma = (const float*)d_in[1];
    const float* ln_beta  = (const float*)d_in[2];
    const float* w_qkv    = (const float*)d_in[3];
    const float* w_out    = (const float*)d_in[4];
    const float* b_out    = (const float*)d_in[5];
    float* out = (float*)d_out;

    void* sp = nullptr;
    cudaGetSymbolAddress(&sp, g_scratch);
    float* xn    = (float*)sp;
    float* qkv   = xn + (size_t)ROWS * D;
    float* ctx   = qkv + (size_t)ROWS * D3;
    float* wqT_r = ctx + (size_t)ROWS * D;
    float* woT_r = wqT_r + (size_t)D * D3;

    cudaFuncSetAttribute(gemm_kernel, cudaFuncAttributeMaxDynamicSharedMemorySize, GEMM_SMEM);
    cudaFuncSetAttribute(attn_kernel, cudaFuncAttributeMaxDynamicSharedMemorySize, ATTN_SMEM);

    // transpose + round weights: W[K][N] -> WT[N][K], tf32 rna
    transpose_round_kernel<<<dim3(D3 / 32, D / 32), dim3(32, 8)>>>(w_qkv, wqT_r, D, D3);
    transpose_round_kernel<<<dim3(D / 32, D / 32), dim3(32, 8)>>>(w_out, woT_r, D, D);

    // 1. LayerNorm (tf32-rounded output)
    ln_kernel<<<ROWS, 256>>>(x, ln_gamma, ln_beta, xn);

    // 2. QKV projection (tensor cores, tf32-rounded output)
    gemm_kernel<<<dim3(D3 / 128, ROWS / 128), 256, GEMM_SMEM>>>(
        xn, wqT_r, nullptr, qkv, D3, 1);

    // 3. Flash attention (tensor cores, register P, vectorized frags)
    attn_kernel<<<dim3(S / 128, HEADS, B), 256, ATTN_SMEM>>>(qkv, ctx);

    // 4. Output projection + bias (tensor cores, full fp32 out)
    gemm_kernel<<<dim3(D / 128, ROWS / 128), 256, GEMM_SMEM>>>(
        ctx, woT_r, b_out, out, D, 0);
}

// round 8
// speedup vs baseline: 1.2675x; 1.0621x over previous
#include <cuda_runtime.h>
#include <cstdint>
#include <math.h>

// Problem constants
#define B       2
#define S       2048
#define D       1024
#define HEADS   16
#define DH      64
#define INNER   1024
#define D3      3072
#define ROWS    4096
#define LN_EPS  1e-5f
// 0.125 * log2(e): folded into Q so softmax runs in base 2
#define QSCALE_LOG2E 0.18033688011112042f

// Scratch: xn | qkv | ctx | w_qkv rounded | w_out rounded
__device__ float g_scratch[(size_t)ROWS * D + (size_t)ROWS * D3 + (size_t)ROWS * D
                           + (size_t)D * D3 + (size_t)D * D];

// ---------------------------------------------------------------------------
// Helpers
// ---------------------------------------------------------------------------
__device__ __forceinline__ uint32_t smem_u32(const void* p) {
    uint32_t a;
    asm("{ .reg .u64 t; cvta.to.shared.u64 t, %1; cvt.u32.u64 %0, t; }" : "=r"(a) : "l"(p));
    return a;
}
__device__ __forceinline__ float tf32r(float x) {
    uint32_t o;
    asm("cvt.rna.tf32.f32 %0, %1;" : "=r"(o) : "f"(x));
    return __uint_as_float(o);
}
__device__ __forceinline__ float ex2f(float x) {
    float r;
    asm("ex2.approx.ftz.f32 %0, %1;" : "=f"(r) : "f"(x));
    return r;
}

#define CP_ASYNC16(dst, src) \
    asm volatile("cp.async.cg.shared.global [%0], [%1], 16;" :: "r"(dst), "l"(src))
#define CP_COMMIT()  asm volatile("cp.async.commit_group;" ::: "memory")
#define CP_WAIT1()   asm volatile("cp.async.wait_group 1;" ::: "memory")
#define CP_WAIT0()   asm volatile("cp.async.wait_group 0;" ::: "memory")

__device__ __forceinline__ void mma_tf32(
    float& d0, float& d1, float& d2, float& d3,
    uint32_t a0, uint32_t a1, uint32_t a2, uint32_t a3,
    uint32_t b0, uint32_t b1)
{
    asm volatile(
        "mma.sync.aligned.m16n8k8.row.col.f32.tf32.tf32.f32 "
        "{%0,%1,%2,%3}, {%4,%5,%6,%7}, {%8,%9}, {%0,%1,%2,%3};"
        : "+f"(d0), "+f"(d1), "+f"(d2), "+f"(d3)
        : "r"(a0), "r"(a1), "r"(a2), "r"(a3), "r"(b0), "r"(b1));
}
#define U(x) __float_as_uint(x)

// ---------------------------------------------------------------------------
// LayerNorm (output rounded to tf32)
// ---------------------------------------------------------------------------
__global__ __launch_bounds__(256) void ln_kernel(
    const float* __restrict__ x, const float* __restrict__ gamma,
    const float* __restrict__ beta, float* __restrict__ y)
{
    const int row = blockIdx.x;
    const int t = threadIdx.x;
    const float4* xp = (const float4*)(x + (size_t)row * D);
    float4 v = xp[t];
    float s  = v.x + v.y + v.z + v.w;
    float ss = v.x * v.x + v.y * v.y + v.z * v.z + v.w * v.w;
    #pragma unroll
    for (int off = 16; off > 0; off >>= 1) {
        s  += __shfl_down_sync(0xffffffffu, s,  off);
        ss += __shfl_down_sync(0xffffffffu, ss, off);
    }
    __shared__ float sh_s[8], sh_ss[8];
    const int w = t >> 5, lane = t & 31;
    if (lane == 0) { sh_s[w] = s; sh_ss[w] = ss; }
    __syncthreads();
    __shared__ float mu_sh, rstd_sh;
    if (t == 0) {
        float S0 = 0.f, SS0 = 0.f;
        #pragma unroll
        for (int i = 0; i < 8; i++) { S0 += sh_s[i]; SS0 += sh_ss[i]; }
        const float mu  = S0 * (1.0f / D);
        const float var = SS0 * (1.0f / D) - mu * mu;
        mu_sh = mu;
        rstd_sh = rsqrtf(var + LN_EPS);
    }
    __syncthreads();
    const float mu = mu_sh, rstd = rstd_sh;
    float4 g  = ((const float4*)gamma)[t];
    float4 bb = ((const float4*)beta)[t];
    float4 o;
    o.x = tf32r((v.x - mu) * rstd * g.x + bb.x);
    o.y = tf32r((v.y - mu) * rstd * g.y + bb.y);
    o.z = tf32r((v.z - mu) * rstd * g.z + bb.z);
    o.w = tf32r((v.w - mu) * rstd * g.w + bb.w);
    ((float4*)(y + (size_t)row * D))[t] = o;
}

// ---------------------------------------------------------------------------
// Round a weight array to tf32 (rna)
// ---------------------------------------------------------------------------
__global__ __launch_bounds__(256) void round_kernel(
    const float* __restrict__ src, float* __restrict__ dst, int n4)
{
    int i = blockIdx.x * 256 + threadIdx.x;
    if (i < n4) {
        float4 v = ((const float4*)src)[i];
        v.x = tf32r(v.x); v.y = tf32r(v.y); v.z = tf32r(v.z); v.w = tf32r(v.w);
        ((float4*)dst)[i] = v;
    }
}

// ---------------------------------------------------------------------------
// TF32 mma.sync GEMM: C[M,N] = A[M,K=1024] @ W[K,N] (+bias)
// 128x128 tile, BK=32, 256 threads (8 warps, warp-tile 32x64), cp.async x2.
// (R3-exact version: fastest measured, 197.7us on QKV)
// ---------------------------------------------------------------------------
#define GA_P 36
#define GB_P 136
#define GA_ST (128 * GA_P)
#define GB_ST (32 * GB_P)
#define GEMM_SMEM ((2 * GA_ST + 2 * GB_ST) * 4)   // 71680 B

__global__ __launch_bounds__(256, 2) void gemm_kernel(
    const float* __restrict__ A, const float* __restrict__ W,
    const float* __restrict__ bias, float* __restrict__ C,
    int N, int round_out)
{
    extern __shared__ float sm[];
    const int tid = threadIdx.x;
    const int wid = tid >> 5, lane = tid & 31;
    const int gID = lane >> 2, tg = lane & 3;
    const int bm = blockIdx.y * 128, bn = blockIdx.x * 128;
    const int wm = (wid & 3) * 32, wn = (wid >> 2) * 64;

    float* Asm[2] = { sm, sm + GA_ST };
    float* Bsm[2] = { sm + 2 * GA_ST, sm + 2 * GA_ST + GB_ST };
    const uint32_t aB[2] = { smem_u32(Asm[0]), smem_u32(Asm[1]) };
    const uint32_t bB[2] = { smem_u32(Bsm[0]), smem_u32(Bsm[1]) };

    float acc[2][8][4];
    #pragma unroll
    for (int im = 0; im < 2; im++)
        #pragma unroll
        for (int n = 0; n < 8; n++)
            #pragma unroll
            for (int j = 0; j < 4; j++) acc[im][n][j] = 0.f;

    // prologue: chunks 0,1
    #pragma unroll
    for (int pi = 0; pi < 2; pi++) {
        const int k0 = pi * 32;
        #pragma unroll
        for (int j = 0; j < 4; j++) {
            const int idx = tid + j * 256;
            const int r = idx >> 3, c = idx & 7;
            CP_ASYNC16(aB[pi] + (uint32_t)(r * GA_P + c * 4) * 4u,
                       A + (size_t)(bm + r) * D + k0 + c * 4);
        }
        #pragma unroll
        for (int j = 0; j < 4; j++) {
            const int idx = tid + j * 256;
            const int r = idx >> 5, c = idx & 31;
            CP_ASYNC16(bB[pi] + (uint32_t)(r * GB_P + c * 4) * 4u,
                       W + (size_t)(k0 + r) * N + bn + c * 4);
        }
        CP_COMMIT();
    }

    for (int i = 0; i < 32; i++) {
        const int s = i & 1;
        if (i < 31) { CP_WAIT1(); } else { CP_WAIT0(); }
        __syncthreads();
        const float* as = Asm[s];
        const float* bs = Bsm[s];
        #pragma unroll
        for (int ks = 0; ks < 4; ks++) {
            const int k = ks * 8;
            uint32_t af[2][4];
            #pragma unroll
            for (int im = 0; im < 2; im++) {
                const float* p = as + (wm + im * 16 + gID) * GA_P + k + tg;
                af[im][0] = U(p[0]);
                af[im][1] = U(p[8 * GA_P]);
                af[im][2] = U(p[4]);
                af[im][3] = U(p[8 * GA_P + 4]);
            }
            #pragma unroll
            for (int n = 0; n < 8; n++) {
                const float* p = bs + (k + tg) * GB_P + wn + n * 8 + gID;
                const uint32_t b0 = U(p[0]);
                const uint32_t b1 = U(p[4 * GB_P]);
                #pragma unroll
                for (int im = 0; im < 2; im++)
                    mma_tf32(acc[im][n][0], acc[im][n][1], acc[im][n][2], acc[im][n][3],
                             af[im][0], af[im][1], af[im][2], af[im][3], b0, b1);
            }
        }
        __syncthreads();
        if (i + 2 < 32) {
            const int k0 = (i + 2) * 32;
            #pragma unroll
            for (int j = 0; j < 4; j++) {
                const int idx = tid + j * 256;
                const int r = idx >> 3, c = idx & 7;
                CP_ASYNC16(aB[s] + (uint32_t)(r * GA_P + c * 4) * 4u,
                           A + (size_t)(bm + r) * D + k0 + c * 4);
            }
            #pragma unroll
            for (int j = 0; j < 4; j++) {
                const int idx = tid + j * 256;
                const int r = idx >> 5, c = idx & 31;
                CP_ASYNC16(bB[s] + (uint32_t)(r * GB_P + c * 4) * 4u,
                           W + (size_t)(k0 + r) * N + bn + c * 4);
            }
            CP_COMMIT();
        }
    }

    // epilogue
    #pragma unroll
    for (int im = 0; im < 2; im++) {
        const int r0 = bm + wm + im * 16 + gID;
        #pragma unroll
        for (int n = 0; n < 8; n++) {
            const int col = bn + wn + n * 8 + 2 * tg;
            float v0 = acc[im][n][0], v1 = acc[im][n][1];
            float v2 = acc[im][n][2], v3 = acc[im][n][3];
            if (bias) {
                const float b0 = bias[col], b1 = bias[col + 1];
                v0 += b0; v1 += b1; v2 += b0; v3 += b1;
            }
            if (round_out) {
                v0 = tf32r(v0); v1 = tf32r(v1); v2 = tf32r(v2); v3 = tf32r(v3);
            }
            *(float2*)&C[(size_t)r0 * N + col]       = make_float2(v0, v1);
            *(float2*)&C[(size_t)(r0 + 8) * N + col] = make_float2(v2, v3);
        }
    }
}

// ---------------------------------------------------------------------------
// TF32 mma.sync flash attention — register-resident P, d-permuted K frags
// (LDS.128), base-2 softmax (log2e folded into Q, raw ex2.approx).
// Block: 256 threads / 8 warps, 128 queries (16/warp), 64-key tiles, 2-stage.
// grid (S/128, HEADS, B)
// ---------------------------------------------------------------------------
#define KP 80
#define VP 68
#define K_ST (64 * KP)
#define V_ST (64 * VP)
#define ATTN_SMEM ((2 * K_ST + 2 * V_ST) * 4)   // 75776 B

__global__ __launch_bounds__(256, 2) void attn_kernel(
    const float* __restrict__ qkv, float* __restrict__ ctx)
{
    extern __shared__ float sm[];
    float* Ksm[2] = { sm, sm + K_ST };
    float* Vsm[2] = { sm + 2 * K_ST, sm + 2 * K_ST + V_ST };
    const uint32_t kB[2] = { smem_u32(Ksm[0]), smem_u32(Ksm[1]) };
    const uint32_t vB[2] = { smem_u32(Vsm[0]), smem_u32(Vsm[1]) };

    const int tid = threadIdx.x;
    const int wid = tid >> 5, lane = tid & 31;
    const int gID = lane >> 2, tg = lane & 3;
    const int h = blockIdx.y, bb = blockIdx.z;
    const int qbase = blockIdx.x * 128 + wid * 16;

    const float* qp = qkv + (size_t)(bb * S + qbase) * D3 + h * DH;
    const float* kbase = qkv + (size_t)bb * S * D3 + INNER + h * DH;
    const float* vbase = kbase + INNER;

    // Q fragments: d-permuted float4 loads; fold 0.125*log2e, rna-round to tf32
    float4 qf[4][2];
    #pragma unroll
    for (int kg = 0; kg < 4; kg++) {
        float4 v0 = *(const float4*)(qp + (size_t)gID * D3 + kg * 16 + 4 * tg);
        float4 v1 = *(const float4*)(qp + (size_t)(gID + 8) * D3 + kg * 16 + 4 * tg);
        v0.x = tf32r(v0.x * QSCALE_LOG2E); v0.y = tf32r(v0.y * QSCALE_LOG2E);
        v0.z = tf32r(v0.z * QSCALE_LOG2E); v0.w = tf32r(v0.w * QSCALE_LOG2E);
        v1.x = tf32r(v1.x * QSCALE_LOG2E); v1.y = tf32r(v1.y * QSCALE_LOG2E);
        v1.z = tf32r(v1.z * QSCALE_LOG2E); v1.w = tf32r(v1.w * QSCALE_LOG2E);
        qf[kg][0] = v0; qf[kg][1] = v1;
    }

    float o[8][4];
    #pragma unroll
    for (int n = 0; n < 8; n++)
        #pragma unroll
        for (int j = 0; j < 4; j++) o[n][j] = 0.f;
    float m0 = -1e30f, m1 = -1e30f, l0 = 0.f, l1 = 0.f;

    // prologue: tiles 0,1
    #pragma unroll
    for (int pi = 0; pi < 2; pi++) {
        const int r0 = pi * 64;
        #pragma unroll
        for (int j = 0; j < 4; j++) {
            const int idx = tid + j * 256;
            const int r = idx >> 4, c = (idx & 15) * 4;
            CP_ASYNC16(kB[pi] + (uint32_t)(r * KP + c) * 4u,
                       kbase + (size_t)(r0 + r) * D3 + c);
            CP_ASYNC16(vB[pi] + (uint32_t)(r * VP + c) * 4u,
                       vbase + (size_t)(r0 + r) * D3 + c);
        }
        CP_COMMIT();
    }

    for (int i = 0; i < 32; i++) {
        const int s = i & 1;
        if (i < 31) { CP_WAIT1(); } else { CP_WAIT0(); }
        __syncthreads();

        // ---- S = Q @ K^T  (d-permuted fragments, base-2 scaled) ----
        float sa[8][4];
        #pragma unroll
        for (int n = 0; n < 8; n++)
            #pragma unroll
            for (int j = 0; j < 4; j++) sa[n][j] = 0.f;
        const float* ks = Ksm[s];
        #pragma unroll
        for (int kg = 0; kg < 4; kg++) {
            #pragma unroll
            for (int n = 0; n < 8; n++) {
                const float4 kv = *(const float4*)(ks + (n * 8 + gID) * KP + kg * 16 + 4 * tg);
                mma_tf32(sa[n][0], sa[n][1], sa[n][2], sa[n][3],
                         U(qf[kg][0].x), U(qf[kg][1].x), U(qf[kg][0].y), U(qf[kg][1].y),
                         U(kv.x), U(kv.y));
                mma_tf32(sa[n][0], sa[n][1], sa[n][2], sa[n][3],
                         U(qf[kg][0].z), U(qf[kg][1].z), U(qf[kg][0].w), U(qf[kg][1].w),
                         U(kv.z), U(kv.w));
            }
        }

        // ---- online softmax in base 2 (P in registers, tf32-rounded) ----
        float rmax0 = sa[0][0], rmax1 = sa[0][2];
        #pragma unroll
        for (int n = 0; n < 8; n++) {
            rmax0 = fmaxf(rmax0, fmaxf(sa[n][0], sa[n][1]));
            rmax1 = fmaxf(rmax1, fmaxf(sa[n][2], sa[n][3]));
        }
        rmax0 = fmaxf(rmax0, __shfl_xor_sync(0xffffffffu, rmax0, 1));
        rmax0 = fmaxf(rmax0, __shfl_xor_sync(0xffffffffu, rmax0, 2));
        rmax1 = fmaxf(rmax1, __shfl_xor_sync(0xffffffffu, rmax1, 1));
        rmax1 = fmaxf(rmax1, __shfl_xor_sync(0xffffffffu, rmax1, 2));
        const float nm0 = fmaxf(m0, rmax0), nm1 = fmaxf(m1, rmax1);
        const float c0 = ex2f(m0 - nm0), c1 = ex2f(m1 - nm1);
        m0 = nm0; m1 = nm1;
        float s0 = 0.f, s1 = 0.f;
        #pragma unroll
        for (int n = 0; n < 8; n++) {
            const float p0 = ex2f(sa[n][0] - m0);
            const float p1 = ex2f(sa[n][1] - m0);
            const float p2 = ex2f(sa[n][2] - m1);
            const float p3 = ex2f(sa[n][3] - m1);
            s0 += p0 + p1; s1 += p2 + p3;
            sa[n][0] = tf32r(p0); sa[n][1] = tf32r(p1);
            sa[n][2] = tf32r(p2); sa[n][3] = tf32r(p3);
            o[n][0] *= c0; o[n][1] *= c0; o[n][2] *= c1; o[n][3] *= c1;
        }
        s0 += __shfl_xor_sync(0xffffffffu, s0, 1);
        s0 += __shfl_xor_sync(0xffffffffu, s0, 2);
        s1 += __shfl_xor_sync(0xffffffffu, s1, 1);
        s1 += __shfl_xor_sync(0xffffffffu, s1, 2);
        l0 = l0 * c0 + s0;
        l1 = l1 * c1 + s1;

        // ---- O += P @ V  (key-relabel: S acc IS the A fragment) ----
        const float* vs = Vsm[s];
        #pragma unroll
        for (int kf = 0; kf < 8; kf++) {
            const uint32_t a0 = U(sa[kf][0]);
            const uint32_t a1 = U(sa[kf][2]);
            const uint32_t a2 = U(sa[kf][1]);
            const uint32_t a3 = U(sa[kf][3]);
            #pragma unroll
            for (int n = 0; n < 8; n++) {
                const float* bp = vs + (kf * 8 + 2 * tg) * VP + n * 8 + gID;
                mma_tf32(o[n][0], o[n][1], o[n][2], o[n][3],
                         a0, a1, a2, a3,
                         U(bp[0]), U(bp[VP]));
            }
        }
        __syncthreads();

        if (i + 2 < 32) {
            const int r0 = (i + 2) * 64;
            #pragma unroll
            for (int j = 0; j < 4; j++) {
                const int idx = tid + j * 256;
                const int r = idx >> 4, c = (idx & 15) * 4;
                CP_ASYNC16(kB[s] + (uint32_t)(r * KP + c) * 4u,
                           kbase + (size_t)(r0 + r) * D3 + c);
                CP_ASYNC16(vB[s] + (uint32_t)(r * VP + c) * 4u,
                           vbase + (size_t)(r0 + r) * D3 + c);
            }
            CP_COMMIT();
        }
    }

    // epilogue: normalize and store (rounded: consumed by out-proj mma)
    const float inv0 = 1.f / l0, inv1 = 1.f / l1;
    const size_t grow = (size_t)(bb * S + qbase + gID);
    #pragma unroll
    for (int n = 0; n < 8; n++) {
        const int col = h * DH + n * 8 + 2 * tg;
        *(float2*)&ctx[grow * INNER + col] =
            make_float2(tf32r(o[n][0] * inv0), tf32r(o[n][1] * inv0));
        *(float2*)&ctx[(grow + 8) * INNER + col] =
            make_float2(tf32r(o[n][2] * inv1), tf32r(o[n][3] * inv1));
    }
}

// ---------------------------------------------------------------------------
extern "C" void kernel_launch(void* const* d_in, const int* in_sizes, int n_in,
                              void* d_out, int out_size)
{
    const float* x        = (const float*)d_in[0];
    const float* ln_gamma = (const float*)d_in[1];
    const float* ln_beta  = (const float*)d_in[2];
    const float* w_qkv    = (const float*)d_in[3];
    const float* w_out    = (const float*)d_in[4];
    const float* b_out    = (const float*)d_in[5];
    float* out = (float*)d_out;

    void* sp = nullptr;
    cudaGetSymbolAddress(&sp, g_scratch);
    float* xn   = (float*)sp;
    float* qkv  = xn + (size_t)ROWS * D;
    float* ctx  = qkv + (size_t)ROWS * D3;
    float* wq_r = ctx + (size_t)ROWS * D;
    float* wo_r = wq_r + (size_t)D * D3;

    cudaFuncSetAttribute(gemm_kernel, cudaFuncAttributeMaxDynamicSharedMemorySize, GEMM_SMEM);
    cudaFuncSetAttribute(attn_kernel, cudaFuncAttributeMaxDynamicSharedMemorySize, ATTN_SMEM);

    // round weights to tf32 (unbiased rna)
    round_kernel<<<(D * D3 / 4 + 255) / 256, 256>>>(w_qkv, wq_r, D * D3 / 4);
    round_kernel<<<(D * D / 4 + 255) / 256, 256>>>(w_out, wo_r, D * D / 4);

    // 1. LayerNorm (tf32-rounded output)
    ln_kernel<<<ROWS, 256>>>(x, ln_gamma, ln_beta, xn);

    // 2. QKV projection (tensor cores, tf32-rounded output)
    gemm_kernel<<<dim3(D3 / 128, ROWS / 128), 256, GEMM_SMEM>>>(
        xn, wq_r, nullptr, qkv, D3, 1);

    // 3. Flash attention (tensor cores, register P, base-2 softmax)
    attn_kernel<<<dim3(S / 128, HEADS, B), 256, ATTN_SMEM>>>(qkv, ctx);

    // 4. Output projection + bias (tensor cores, full fp32 out)
    gemm_kernel<<<dim3(D / 128, ROWS / 128), 256, GEMM_SMEM>>>(
        ctx, wo_r, b_out, out, D, 0);
}